// round 4
// baseline (speedup 1.0000x reference)
#include <cuda_runtime.h>

// YOLO postprocess: filter(score>0.5) -> sort desc -> greedy NMS(IoU>0.5) -> masked rows.
// x: (1, 84, 8400) f32 channel-major; out: (8400, 5) f32.
//
//   K0 filter (warp-aggregated compaction)
//   K1 rank-by-counting sort + gather (chip-parallel)
//   K2 IoU suppression bit-matrix (64x64 tiles, upper triangle) + diag words
//   K3 greedy reduction: sparse diagonal chain + streaming producers (1 block)
//   K4 masked output write

#define N_IN   8400
#define NSORT  8192
#define NWORDS 128        // row stride of g_mask (u64 words)
#define FULLW  0xffffffffu

// ---------------- global scratch ----------------
__device__ int    g_cnt;
__device__ unsigned long long g_keys[NSORT];
__device__ __align__(16) float4 g_boxes[NSORT];
__device__ float  g_score[NSORT];
__device__ float  g_area[NSORT];
__device__ unsigned long long g_keepw[NWORDS];
__device__ unsigned long long g_diag[NSORT + 64];       // diag-block word per row
__device__ __align__(16) unsigned long long g_mask[(size_t)NSORT * NWORDS]; // 8 MB

// ---------------- K0: filter + compact (order canonicalized by K1) --------
extern "C" __global__ void __launch_bounds__(256)
k0_filter_kernel(const float* __restrict__ x)
{
    const int n = blockIdx.x * 256 + threadIdx.x;
    bool pass = false;
    float s = 0.f;
    if (n < N_IN) {
        s = x[4 * N_IN + n];
        pass = (s > 0.5f);
    }
    unsigned m = __ballot_sync(FULLW, pass);
    if (!m) return;
    int lane = threadIdx.x & 31;
    int leader = __ffs(m) - 1;
    int base = 0;
    if (lane == leader) base = atomicAdd(&g_cnt, __popc(m));
    base = __shfl_sync(FULLW, base, leader);
    if (pass) {
        int slot = base + __popc(m & ((1u << lane) - 1));
        if (slot < NSORT) {
            unsigned sb = __float_as_uint(s);
            g_keys[slot] = ((unsigned long long)(~sb) << 32) | (unsigned)n;
        }
    }
}

// ---------------- K1: rank-by-counting sort + gather ----------------------
// keys unique (idx in low bits) => rank is an exact permutation.
// key = (~score_bits)<<32 | idx : ascending == descending score, stable ties.
extern "C" __global__ void __launch_bounds__(64)
k1_rank_kernel(const float* __restrict__ x)
{
    __shared__ unsigned long long tile[64];
    const int M = min(g_cnt, NSORT);
    if ((int)(blockIdx.x * 64) >= M) return;          // uniform block early-exit

    const int t = blockIdx.x * 64 + threadIdx.x;
    unsigned long long mykey = (t < M) ? g_keys[t] : ~0ULL;
    int rank = 0;
    for (int base = 0; base < M; base += 64) {
        int c = base + threadIdx.x;
        tile[threadIdx.x] = (c < M) ? g_keys[c] : ~0ULL;  // sentinel never counts
        __syncthreads();
#pragma unroll 16
        for (int j = 0; j < 64; j++)
            rank += (tile[j] < mykey);
        __syncthreads();
    }

    if (t < M) {
        int idx = (int)(unsigned)mykey;
        float X1 = x[idx];
        float Y1 = x[N_IN + idx];
        float X2 = x[2 * N_IN + idx];
        float Y2 = x[3 * N_IN + idx];
        g_boxes[rank] = make_float4(X1, Y1, X2, Y2);
        g_score[rank] = __uint_as_float(~(unsigned)(mykey >> 32));
        g_area[rank]  = (X2 - X1) * (Y2 - Y1);
    }
}

// ---------------- K2: suppression bit-matrix (64x64 tiles) ----------------
// mask[i][bx] bit c set <=> j=bx*64+c suppressible by i (j>i, IoU>0.5).
// IoU > 0.5 <=> 3*inter > area_i + area_j + 1e-9 (denominator always > 0).
// Diagonal tiles also write g_diag[i] (bits strictly above the diagonal).
extern "C" __global__ void __launch_bounds__(64, 16)
k2_mask_kernel()
{
    const int bx = blockIdx.x, by = blockIdx.y;
    if (bx < by) return;
    const int M = min(g_cnt, NSORT);
    const int nct = (M + 63) >> 6;
    if (by >= nct || bx >= nct) return;

    __shared__ float4 cb[64];
    __shared__ float  ca[64];
    const int t  = threadIdx.x;
    const int j0 = bx << 6;
    cb[t] = g_boxes[j0 + t];
    ca[t] = g_area[j0 + t];
    __syncthreads();

    const int i = (by << 6) + t;
    if (i >= M) return;
    const float4 b  = g_boxes[i];
    const float  sA = g_area[i] + 1e-9f;
    const int    nc = min(64, M - j0);

    unsigned long long bits = 0;
#pragma unroll 8
    for (int c = 0; c < nc; c++) {
        float4 q = cb[c];
        float iw = fminf(b.z, q.z) - fmaxf(b.x, q.x);
        float ih = fminf(b.w, q.w) - fmaxf(b.y, q.y);
        float inter = fmaxf(iw, 0.f) * fmaxf(ih, 0.f);
        bool sup = ((j0 + c) > i) && (3.0f * inter > sA + ca[c]);
        if (sup) bits |= 1ULL << c;
    }
    g_mask[(size_t)i * NWORDS + bx] = bits;
    if (bx == by) g_diag[i] = bits;
}

// ---------------- K3: greedy reduction (sparse diagonal chain) ------------
// Groups of 64 rows (one keep-word each). Per group:
//   R = rem[word g]; for rows with nonzero diag word (ballot-sparse, ascending):
//     if row not yet suppressed in R, R |= diag  (diag bits strictly > row pos
//     => keep word for the whole group is exactly ~R_final).
//   Then OR kept rows' FUTURE words (w > g) into per-lane rem registers.
// Warps 1-7 stream the next group's future-words into double-buffered smem.
#define K3_SMEM (2 * 64 * NWORDS * 8)   // 128 KB

extern "C" __global__ void __launch_bounds__(256, 1)
k3_greedy_kernel()
{
    extern __shared__ unsigned long long sbuf[];   // [2][64][128]
    const int M = min(g_cnt, NSORT);
    const int tid = threadIdx.x, wid = tid >> 5, lane = tid & 31;
    const int ngroups = (M + 63) >> 6;             // == nwords
    if (ngroups == 0) return;
    const int nwords  = ngroups;
    const int nw2     = (nwords + 1) & ~1;         // even pad (stride 128 ok)

    // producers: copy rows of group g, words [g&~1, nw2) (16B chunks)
    auto cpgroup = [&](int g) {
        const int base = g << 6;
        const int w2lo = (g & ~1) >> 1;
        const int w2hi = nw2 >> 1;
        unsigned long long* dst0 = &sbuf[(g & 1) * (64 * NWORDS)];
        for (int r = wid - 1; r < 64; r += 7) {
            const ulonglong2* src = (const ulonglong2*)&g_mask[(size_t)(base + r) * NWORDS];
            ulonglong2* dst = (ulonglong2*)&dst0[r * NWORDS];
            for (int w2 = w2lo + lane; w2 < w2hi; w2 += 32)
                dst[w2] = src[w2];
        }
    };

    if (wid != 0) cpgroup(0);

    // consumer: prefetch group-0 diag words
    unsigned long long dA = 0, dB = 0;
    unsigned long long rem0 = 0, rem1 = 0, rem2 = 0, rem3 = 0;
    if (wid == 0) {
        dA = g_diag[lane];
        dB = g_diag[32 + lane];
    }
    __syncthreads();

    for (int g = 0; g < ngroups; g++) {
        if (wid != 0) {
            if (g + 1 < ngroups) cpgroup(g + 1);
        } else {
            const int base = g << 6;
            // prefetch next group's diag
            unsigned long long nA = g_diag[base + 64 + lane];
            unsigned long long nB = g_diag[base + 96 + lane];

            // fetch rem word g
            const int slot = g >> 5, owner = g & 31;
            unsigned long long mine = (slot == 0) ? rem0 : (slot == 1) ? rem1
                                    : (slot == 2) ? rem2 : rem3;
            unsigned long long R = __shfl_sync(FULLW, mine, owner);

            // sparse ascending chain over nonzero diag rows
            unsigned bA = __ballot_sync(FULLW, dA != 0ULL);
            unsigned bB = __ballot_sync(FULLW, dB != 0ULL);
            while (bA) {
                int p = __ffs(bA) - 1; bA &= bA - 1;
                unsigned long long d = __shfl_sync(FULLW, dA, p);
                if (!((R >> p) & 1ULL)) R |= d;
            }
            while (bB) {
                int p = __ffs(bB) - 1; bB &= bB - 1;
                unsigned long long d = __shfl_sync(FULLW, dB, p);
                if (!((R >> (p + 32)) & 1ULL)) R |= d;
            }

            unsigned long long vm =
                (base + 64 <= M) ? ~0ULL : ((1ULL << (M - base)) - 1ULL);
            unsigned long long keepw = ~R & vm;
            if (lane == 0) g_keepw[g] = keepw;

            if (lane == owner) {
                if      (slot == 0) rem0 = R;
                else if (slot == 1) rem1 = R;
                else if (slot == 2) rem2 = R;
                else                rem3 = R;
            }

            // accumulate kept rows' future words into per-lane rem registers
            const unsigned long long* buf = &sbuf[(g & 1) * (64 * NWORDS)];
            const bool a0 = (lane      > g) && (lane      < nwords);
            const bool a1 = (lane + 32 > g) && (lane + 32 < nwords);
            const bool a2 = (lane + 64 > g) && (lane + 64 < nwords);
            const bool a3 = (lane + 96 > g) && (lane + 96 < nwords);
            unsigned long long kw = keepw;
            while (kw) {
                int r = __ffsll((long long)kw) - 1; kw &= kw - 1;
                const unsigned long long* row = buf + r * NWORDS;
                if (a0) rem0 |= row[lane];
                if (a1) rem1 |= row[lane + 32];
                if (a2) rem2 |= row[lane + 64];
                if (a3) rem3 |= row[lane + 96];
            }

            dA = nA; dB = nB;
        }
        __syncthreads();
    }
}

// ---------------- K4: masked output write ----------------
extern "C" __global__ void __launch_bounds__(256)
k4_out_kernel(float* __restrict__ out)
{
    const int r = blockIdx.x * 256 + threadIdx.x;
    if (r >= N_IN) return;
    const int M = min(g_cnt, NSORT);
    if (r < M) {
        float m = (float)((g_keepw[r >> 6] >> (r & 63)) & 1ULL);
        float4 b = g_boxes[r];
        out[r * 5 + 0] = b.x * m;
        out[r * 5 + 1] = b.y * m;
        out[r * 5 + 2] = b.z * m;
        out[r * 5 + 3] = b.w * m;
        out[r * 5 + 4] = g_score[r] * m;
    } else {
        out[r * 5 + 0] = 0.f;
        out[r * 5 + 1] = 0.f;
        out[r * 5 + 2] = 0.f;
        out[r * 5 + 3] = 0.f;
        out[r * 5 + 4] = 0.f;
    }
}

// ---------------- launcher ----------------
extern "C" void kernel_launch(void* const* d_in, const int* in_sizes, int n_in,
                              void* d_out, int out_size)
{
    (void)in_sizes; (void)n_in; (void)out_size;
    const float* x = (const float*)d_in[0];
    float* out = (float*)d_out;

    static void* cnt_addr = nullptr;
    if (!cnt_addr) {
        cudaGetSymbolAddress(&cnt_addr, g_cnt);
        cudaFuncSetAttribute(k3_greedy_kernel,
                             cudaFuncAttributeMaxDynamicSharedMemorySize, K3_SMEM);
    }

    cudaMemsetAsync(cnt_addr, 0, sizeof(int));
    k0_filter_kernel<<<(N_IN + 255) / 256, 256>>>(x);
    k1_rank_kernel<<<NSORT / 64, 64>>>(x);
    k2_mask_kernel<<<dim3(NWORDS, NWORDS), 64>>>();
    k3_greedy_kernel<<<1, 256, K3_SMEM>>>();
    k4_out_kernel<<<(N_IN + 255) / 256, 256>>>(out);
}

// round 5
// speedup vs baseline: 3.6471x; 3.6471x over previous
#include <cuda_runtime.h>

// YOLO postprocess: filter(score>0.5) -> sort desc -> greedy NMS(IoU>0.5) -> masked rows.
// x: (1, 84, 8400) f32 channel-major; out: (8400, 5) f32.
//
//   K0 filter (warp-aggregated compaction)
//   K1 rank-by-counting sort + gather (chip-parallel)
//   K2 sparse suppression EDGE LIST (i<j, IoU>0.5), 64x64 tiles, upper triangle
//   K3 exact greedy via fixed-point status propagation (1 block, smem edges)
//   K4 masked output write
//
// Greedy NMS == unique fixed point of:
//   row j is SUP  iff exists edge (i,j), i<j, with i KEEP
//   row j is KEEP iff every edge (i,j) has i SUP
// Rounds settle rows in dependency-depth order; min-index UNKNOWN row always
// settles, so termination is guaranteed; practical depth ~ cluster chain length.

#define N_IN   8400
#define NSORT  8192
#define FULLW  0xffffffffu
#define ECAP   (1 << 20)      // edge capacity (4 MB scratch; ~25k expected)
#define ESM    40960          // edges cached in smem (160 KB)
#define NB32   256            // 8192 bits / 32

// ---------------- global scratch ----------------
__device__ int    g_cnt;
__device__ int    g_ecnt;
__device__ unsigned long long g_keys[NSORT];
__device__ __align__(16) float4 g_boxes[NSORT];
__device__ float  g_score[NSORT];
__device__ float  g_area[NSORT];
__device__ unsigned g_keepw32[NB32];
__device__ unsigned g_edges[ECAP];

// ---------------- K0: filter + compact (order canonicalized by K1) --------
extern "C" __global__ void __launch_bounds__(256)
k0_filter_kernel(const float* __restrict__ x)
{
    const int n = blockIdx.x * 256 + threadIdx.x;
    bool pass = false;
    float s = 0.f;
    if (n < N_IN) {
        s = x[4 * N_IN + n];
        pass = (s > 0.5f);
    }
    unsigned m = __ballot_sync(FULLW, pass);
    if (!m) return;
    int lane = threadIdx.x & 31;
    int leader = __ffs(m) - 1;
    int base = 0;
    if (lane == leader) base = atomicAdd(&g_cnt, __popc(m));
    base = __shfl_sync(FULLW, base, leader);
    if (pass) {
        int slot = base + __popc(m & ((1u << lane) - 1));
        if (slot < NSORT) {
            unsigned sb = __float_as_uint(s);
            g_keys[slot] = ((unsigned long long)(~sb) << 32) | (unsigned)n;
        }
    }
}

// ---------------- K1: rank-by-counting sort + gather ----------------------
// keys unique (idx in low bits) => rank is an exact permutation.
// key = (~score_bits)<<32 | idx : ascending == descending score, stable ties.
extern "C" __global__ void __launch_bounds__(64)
k1_rank_kernel(const float* __restrict__ x)
{
    __shared__ unsigned long long tile[64];
    const int M = min(g_cnt, NSORT);
    if ((int)(blockIdx.x * 64) >= M) return;          // uniform block early-exit

    const int t = blockIdx.x * 64 + threadIdx.x;
    unsigned long long mykey = (t < M) ? g_keys[t] : ~0ULL;
    int rank = 0;
    for (int base = 0; base < M; base += 64) {
        int c = base + threadIdx.x;
        tile[threadIdx.x] = (c < M) ? g_keys[c] : ~0ULL;  // sentinel never counts
        __syncthreads();
#pragma unroll 16
        for (int j = 0; j < 64; j++)
            rank += (tile[j] < mykey);
        __syncthreads();
    }

    if (t < M) {
        int idx = (int)(unsigned)mykey;
        float X1 = x[idx];
        float Y1 = x[N_IN + idx];
        float X2 = x[2 * N_IN + idx];
        float Y2 = x[3 * N_IN + idx];
        g_boxes[rank] = make_float4(X1, Y1, X2, Y2);
        g_score[rank] = __uint_as_float(~(unsigned)(mykey >> 32));
        g_area[rank]  = (X2 - X1) * (Y2 - Y1);
    }
}

// ---------------- K2: sparse suppression edges (64x64 tiles) --------------
// Edge (i, j), i<j, packed (i<<13)|j, when IoU>0.5:
//   IoU > 0.5 <=> 3*inter > area_i + area_j + 1e-9 (denominator always > 0).
extern "C" __global__ void __launch_bounds__(64)
k2_edges_kernel()
{
    const int bx = blockIdx.x, by = blockIdx.y;
    if (bx < by) return;
    const int M = min(g_cnt, NSORT);
    const int nct = (M + 63) >> 6;
    if (by >= nct || bx >= nct) return;

    __shared__ float4 cb[64];
    __shared__ float  ca[64];
    __shared__ unsigned ebuf[4096];     // worst case: full 64x64 tile
    __shared__ int ec, gbase;
    const int t  = threadIdx.x;
    if (t == 0) ec = 0;
    const int j0 = bx << 6;
    cb[t] = g_boxes[j0 + t];
    ca[t] = g_area[j0 + t];
    __syncthreads();

    const int i = (by << 6) + t;
    if (i < M) {
        const float4 b  = g_boxes[i];
        const float  sA = g_area[i] + 1e-9f;
        const int    nc = min(64, M - j0);
        const int    c0 = (bx == by) ? (t + 1) : 0;   // strict upper triangle
        for (int c = c0; c < nc; c++) {
            float4 q = cb[c];
            float iw = fminf(b.z, q.z) - fmaxf(b.x, q.x);
            float ih = fminf(b.w, q.w) - fmaxf(b.y, q.y);
            float inter = fmaxf(iw, 0.f) * fmaxf(ih, 0.f);
            if (3.0f * inter > sA + ca[c]) {
                int p = atomicAdd(&ec, 1);
                ebuf[p] = ((unsigned)i << 13) | (unsigned)(j0 + c);
            }
        }
    }
    __syncthreads();
    if (t == 0 && ec > 0) gbase = atomicAdd(&g_ecnt, ec);
    __syncthreads();
    for (int p = t; p < ec; p += 64) {
        int gp = gbase + p;
        if (gp < ECAP) g_edges[gp] = ebuf[p];
    }
}

// ---------------- K3: exact greedy via fixed-point propagation ------------
#define K3_SMEM (ESM * 4)     // 160 KB edge cache

extern "C" __global__ void __launch_bounds__(1024, 1)
k3_fixed_kernel()
{
    extern __shared__ unsigned se[];                  // [ESM]
    __shared__ unsigned keepb[NB32], supb[NB32], nsup[NB32], unkp[NB32];
    __shared__ int notdone;
    const int M   = min(g_cnt, NSORT);
    const int tid = threadIdx.x;
    int E = g_ecnt; if (E > ECAP) E = ECAP;
    const int Es = min(E, ESM);

    for (int e = tid; e < Es; e += 1024) se[e] = g_edges[e];
    if (tid < NB32) { keepb[tid] = 0u; supb[tid] = 0u; }
    __syncthreads();

    for (int round = 0; round < NSORT; round++) {
        if (tid < NB32) { nsup[tid] = 0u; unkp[tid] = 0u; }
        if (tid == 0) notdone = 0;
        __syncthreads();

        for (int e = tid; e < E; e += 1024) {
            unsigned ed = (e < ESM) ? se[e] : g_edges[e];
            int i = (int)(ed >> 13), j = (int)(ed & 8191u);
            unsigned jset = (keepb[j >> 5] | supb[j >> 5]) >> (j & 31);
            if (jset & 1u) continue;                          // j settled
            if ((keepb[i >> 5] >> (i & 31)) & 1u)
                atomicOr(&nsup[j >> 5], 1u << (j & 31));      // KEEP pred -> SUP
            else if (!((supb[i >> 5] >> (i & 31)) & 1u))
                atomicOr(&unkp[j >> 5], 1u << (j & 31));      // UNKNOWN pred
        }
        __syncthreads();

        if (tid < NB32) {
            int base = tid << 5;
            unsigned valid = (base + 32 <= M) ? 0xffffffffu
                           : (base >= M ? 0u : ((1u << (M - base)) - 1u));
            unsigned unk = ~(keepb[tid] | supb[tid]) & valid;
            if (unk) {
                unsigned ns = nsup[tid] & unk;
                unsigned nk = unk & ~nsup[tid] & ~unkp[tid];
                supb[tid]  |= ns;
                keepb[tid] |= nk;
                if (unk & ~(ns | nk)) notdone = 1;            // benign race
            }
        }
        __syncthreads();
        if (!notdone) break;
    }

    if (tid < NB32) g_keepw32[tid] = keepb[tid];
}

// ---------------- K4: masked output write ----------------
extern "C" __global__ void __launch_bounds__(256)
k4_out_kernel(float* __restrict__ out)
{
    const int r = blockIdx.x * 256 + threadIdx.x;
    if (r >= N_IN) return;
    const int M = min(g_cnt, NSORT);
    if (r < M) {
        float m = (float)((g_keepw32[r >> 5] >> (r & 31)) & 1u);
        float4 b = g_boxes[r];
        out[r * 5 + 0] = b.x * m;
        out[r * 5 + 1] = b.y * m;
        out[r * 5 + 2] = b.z * m;
        out[r * 5 + 3] = b.w * m;
        out[r * 5 + 4] = g_score[r] * m;
    } else {
        out[r * 5 + 0] = 0.f;
        out[r * 5 + 1] = 0.f;
        out[r * 5 + 2] = 0.f;
        out[r * 5 + 3] = 0.f;
        out[r * 5 + 4] = 0.f;
    }
}

// ---------------- launcher ----------------
extern "C" void kernel_launch(void* const* d_in, const int* in_sizes, int n_in,
                              void* d_out, int out_size)
{
    (void)in_sizes; (void)n_in; (void)out_size;
    const float* x = (const float*)d_in[0];
    float* out = (float*)d_out;

    static void* cnt_addr = nullptr;
    static void* ecnt_addr = nullptr;
    if (!cnt_addr) {
        cudaGetSymbolAddress(&cnt_addr, g_cnt);
        cudaGetSymbolAddress(&ecnt_addr, g_ecnt);
        cudaFuncSetAttribute(k3_fixed_kernel,
                             cudaFuncAttributeMaxDynamicSharedMemorySize, K3_SMEM);
    }

    cudaMemsetAsync(cnt_addr, 0, sizeof(int));
    cudaMemsetAsync(ecnt_addr, 0, sizeof(int));
    k0_filter_kernel<<<(N_IN + 255) / 256, 256>>>(x);
    k1_rank_kernel<<<NSORT / 64, 64>>>(x);
    k2_edges_kernel<<<dim3(NSORT / 64, NSORT / 64), 64>>>();
    k3_fixed_kernel<<<1, 1024, K3_SMEM>>>();
    k4_out_kernel<<<(N_IN + 255) / 256, 256>>>(out);
}